// round 1
// baseline (speedup 1.0000x reference)
#include <cuda_runtime.h>
#include <cstdint>

// ---------------- problem constants ----------------
namespace {
constexpr int B    = 2;
constexpr int C0   = 64;     // input channels after pool
constexpr int C1   = 128;    // main channel count
constexpr int H    = 128, W = 128;
constexpr int HW   = H * W;            // 16384
constexpr int NPIX = B * HW;           // 32768
constexpr int R2   = 256;              // 16x16 reduced K/V
constexpr int DH   = 32;               // dim_head
constexpr float BN_EPS = 1e-5f;
}

// ---------------- scratch (static device, no allocs) ----------------
__device__ float g_pool[B * C0 * HW];        // pooled input
__device__ float g_t   [B * C1 * HW];        // bn outputs / attn out
__device__ float g_u   [B * C1 * HW];        // conv3x3 out / dw out
__device__ float g_o   [B * C1 * HW];        // running residual "out"
__device__ float g_qkv [B * 3 * C1 * HW];    // qkv (384 ch)
__device__ float g_kd  [B * C1 * R2];        // downsampled k
__device__ float g_vd  [B * C1 * R2];        // downsampled v
__device__ float g_A   [C1];                 // per-channel BN scale
__device__ float g_Bv  [C1];                 // per-channel BN shift

// ---------------- maxpool 2x2 (256x256 -> 128x128) ----------------
__global__ void k_maxpool(const float* __restrict__ x, float* __restrict__ out) {
    int i = blockIdx.x * 256 + threadIdx.x;          // over B*C0*HW
    int p  = i & (HW - 1);
    int bc = i >> 14;
    int y = p >> 7, xx = p & 127;
    const float* ip = x + (size_t)bc * 65536 + (size_t)(y * 2) * 256 + xx * 2;
    out[i] = fmaxf(fmaxf(ip[0], ip[1]), fmaxf(ip[256], ip[257]));
}

// ---------------- BN stats: one block per channel ----------------
__global__ void k_bnstats(const float* __restrict__ x, const float* __restrict__ gg,
                          const float* __restrict__ bb, int Cc) {
    int c = blockIdx.x;
    int tid = threadIdx.x;
    const float* x0 = x + (size_t)c * HW;            // b = 0
    const float* x1 = x + (size_t)(Cc + c) * HW;     // b = 1
    float s = 0.f, s2 = 0.f;
    for (int p = tid; p < HW; p += 256) {
        float a = x0[p]; s += a; s2 = fmaf(a, a, s2);
        float d = x1[p]; s += d; s2 = fmaf(d, d, s2);
    }
    __shared__ double rs[256], rq[256];
    rs[tid] = (double)s; rq[tid] = (double)s2;
    __syncthreads();
    for (int off = 128; off > 0; off >>= 1) {
        if (tid < off) { rs[tid] += rs[tid + off]; rq[tid] += rq[tid + off]; }
        __syncthreads();
    }
    if (tid == 0) {
        double mean = rs[0] / (double)NPIX;
        double var  = rq[0] / (double)NPIX - mean * mean;
        double A    = (double)gg[c] / sqrt(var + (double)BN_EPS);
        g_A[c]  = (float)A;
        g_Bv[c] = (float)((double)bb[c] - mean * A);
    }
}

// ---------------- BN apply (+ optional relu) ----------------
__global__ void k_bnapply(const float* __restrict__ x, float* __restrict__ y,
                          int Cc, int relu) {
    int i = blockIdx.x * 256 + threadIdx.x;
    int c = (i >> 14) % Cc;
    float v = fmaf(x[i], g_A[c], g_Bv[c]);
    if (relu) v = fmaxf(v, 0.f);
    y[i] = v;
}

// ---------------- direct 3x3 conv, pad=1, COUT=128 ----------------
// block (16,16); tile 32x32 pixels; 8 co + 2x2 px per thread.
template <int CIN>
__global__ void k_conv3(const float* __restrict__ in, const float* __restrict__ w,
                        float* __restrict__ out) {
    __shared__ float s_in[34 * 34];
    __shared__ float s_w[72];
    int tx = threadIdx.x, ty = threadIdx.y;
    int tid = ty * 16 + tx;
    int bz = blockIdx.z;
    int b   = bz >> 4;
    int co0 = (bz & 15) * 8;
    int y0 = blockIdx.y * 32, x0 = blockIdx.x * 32;
    float acc[8][4];
#pragma unroll
    for (int k = 0; k < 8; k++) { acc[k][0]=acc[k][1]=acc[k][2]=acc[k][3]=0.f; }
    int sy = ty * 2, sx = tx * 2;
    for (int ci = 0; ci < CIN; ci++) {
        const float* ip = in + (size_t)(b * CIN + ci) * HW;
        for (int i = tid; i < 34 * 34; i += 256) {
            int iy = i / 34, ix = i - iy * 34;
            int gy = y0 + iy - 1, gx = x0 + ix - 1;
            float v = 0.f;
            if ((unsigned)gy < 128u && (unsigned)gx < 128u) v = ip[gy * 128 + gx];
            s_in[i] = v;
        }
        if (tid < 72) {
            int k = tid / 9, q = tid - k * 9;
            s_w[tid] = w[((size_t)(co0 + k) * CIN + ci) * 9 + q];
        }
        __syncthreads();
#pragma unroll
        for (int dy = 0; dy < 3; dy++)
#pragma unroll
            for (int dx = 0; dx < 3; dx++) {
                float i00 = s_in[(sy + dy) * 34 + sx + dx];
                float i01 = s_in[(sy + dy) * 34 + sx + dx + 1];
                float i10 = s_in[(sy + dy + 1) * 34 + sx + dx];
                float i11 = s_in[(sy + dy + 1) * 34 + sx + dx + 1];
#pragma unroll
                for (int k = 0; k < 8; k++) {
                    float wv = s_w[k * 9 + dy * 3 + dx];
                    acc[k][0] = fmaf(i00, wv, acc[k][0]);
                    acc[k][1] = fmaf(i01, wv, acc[k][1]);
                    acc[k][2] = fmaf(i10, wv, acc[k][2]);
                    acc[k][3] = fmaf(i11, wv, acc[k][3]);
                }
            }
        __syncthreads();
    }
#pragma unroll
    for (int k = 0; k < 8; k++) {
        float* op = out + (size_t)(b * C1 + co0 + k) * HW;
        op[(y0 + sy) * 128 + x0 + sx]         = acc[k][0];
        op[(y0 + sy) * 128 + x0 + sx + 1]     = acc[k][1];
        op[(y0 + sy + 1) * 128 + x0 + sx]     = acc[k][2];
        op[(y0 + sy + 1) * 128 + x0 + sx + 1] = acc[k][3];
    }
}

// ---------------- 1x1 conv (pointwise GEMV), optional residual add ----------------
// 256 threads, 2 px per thread, 16 co per thread; weights in smem (broadcast).
template <int CIN>
__global__ void k_conv1(const float* __restrict__ in, const float* __restrict__ w,
                        float* __restrict__ out, const float* __restrict__ add,
                        int COUT) {
    __shared__ float s_w[16 * CIN];
    int tid = threadIdx.x;
    int co0 = blockIdx.y * 16;
    for (int i = tid; i < 16 * CIN; i += 256) {
        int k = i / CIN, ci = i - k * CIN;
        s_w[i] = w[(size_t)(co0 + k) * CIN + ci];
    }
    __syncthreads();
    int gq = blockIdx.x * 512 + tid * 2;
    int b = gq >> 14;
    int p = gq & (HW - 1);
    const float* ip = in + (size_t)b * CIN * HW + p;
    float a0[16], a1[16];
#pragma unroll
    for (int k = 0; k < 16; k++) { a0[k] = 0.f; a1[k] = 0.f; }
#pragma unroll 4
    for (int ci = 0; ci < CIN; ci++) {
        float2 xv = *reinterpret_cast<const float2*>(ip + (size_t)ci * HW);
#pragma unroll
        for (int k = 0; k < 16; k++) {
            float wv = s_w[k * CIN + ci];
            a0[k] = fmaf(xv.x, wv, a0[k]);
            a1[k] = fmaf(xv.y, wv, a1[k]);
        }
    }
#pragma unroll
    for (int k = 0; k < 16; k++) {
        size_t idx = (size_t)(b * COUT + co0 + k) * HW + p;
        float v0 = a0[k], v1 = a1[k];
        if (add) { v0 += add[idx]; v1 += add[idx + 1]; }
        out[idx] = v0; out[idx + 1] = v1;
    }
}

// ---------------- depthwise 3x3, pad=1, groups=128 ----------------
__global__ void k_dw3(const float* __restrict__ in, const float* __restrict__ w,
                      float* __restrict__ out) {
    int i = blockIdx.x * 256 + threadIdx.x;   // over B*C1*HW
    int p  = i & (HW - 1);
    int bc = i >> 14;
    int c  = bc & 127;
    int y = p >> 7, x = p & 127;
    const float* ip = in + (size_t)bc * HW;
    const float* wp = w + c * 9;
    float s = 0.f;
#pragma unroll
    for (int dy = 0; dy < 3; dy++) {
        int gy = y + dy - 1;
        if ((unsigned)gy >= 128u) continue;
#pragma unroll
        for (int dx = 0; dx < 3; dx++) {
            int gx = x + dx - 1;
            if ((unsigned)gx >= 128u) continue;
            s = fmaf(ip[gy * 128 + gx], wp[dy * 3 + dx], s);
        }
    }
    out[i] = s;
}

// ---------------- bilinear downsample k,v: 128x128 -> 16x16 (align_corners) ----------------
__global__ void k_ds(const float* __restrict__ qkv) {
    int i = blockIdx.x * 256 + threadIdx.x;   // over B*256*R2 = 131072
    int j  = i & 255;
    int oc = (i >> 8) & 255;
    int b  = i >> 16;
    const float* ip = qkv + ((size_t)(b * 384) + 128 + oc) * HW;
    int r = j >> 4, s = j & 15;
    const float step = (float)(127.0 / 15.0);
    float ph = (float)r * step;
    int   lh = min((int)ph, 126);
    float fh = ph - (float)lh;
    float pw = (float)s * step;
    int   lw = min((int)pw, 126);
    float fw = pw - (float)lw;
    const float* p0 = ip + lh * 128 + lw;
    float v00 = p0[0], v01 = p0[1], v10 = p0[128], v11 = p0[129];
    float val = (1.f - fh) * ((1.f - fw) * v00 + fw * v01)
              +        fh  * ((1.f - fw) * v10 + fw * v11);
    float* dst = (oc < 128) ? g_kd : g_vd;
    int cc = oc & 127;
    dst[(size_t)(b * 128 + cc) * R2 + j] = val;
}

// ---------------- fused attention: one thread per query pixel ----------------
// K,V (256x32 each) + bias table column staged in dynamic smem; all lanes walk
// j in lockstep -> every K/V read is a broadcast LDS.128.
__global__ void k_attn(const float* __restrict__ qkv, const float* __restrict__ table,
                       float* __restrict__ outp) {
    extern __shared__ float sm[];
    float* k_s = sm;                 // [256][32]
    float* v_s = sm + R2 * DH;       // [256][32]
    float* t_s = sm + 2 * R2 * DH;   // [961]
    int tid = threadIdx.x;
    int bh  = blockIdx.y;
    int b = bh >> 2, head = bh & 3;
    for (int i = tid; i < R2 * DH; i += 256) {
        int d = i >> 8, j = i & 255;
        k_s[j * DH + d] = g_kd[((size_t)(b * C1) + d * 4 + head) * R2 + j];
        v_s[j * DH + d] = g_vd[((size_t)(b * C1) + d * 4 + head) * R2 + j];
    }
    for (int i = tid; i < 961; i += 256) t_s[i] = table[i * 4 + head];
    __syncthreads();

    int p = blockIdx.x * 256 + tid;
    float q[DH];
#pragma unroll
    for (int d = 0; d < DH; d++)
        q[d] = qkv[((size_t)(b * 384) + d * 4 + head) * HW + p];
    int rh = p >> 10;            // (y>>3), y = p>>7
    int rw = (p >> 3) & 15;      // (x>>3), x = p&127
    const float scale = 0.17677669529663687f;   // 32^-0.5
    float l = 0.f;
    float o[DH];
#pragma unroll
    for (int d = 0; d < DH; d++) o[d] = 0.f;

    for (int j = 0; j < 256; j++) {
        int jh = j >> 4, jw = j & 15;
        float bias = t_s[(rh - jh + 15) * 31 + (rw - jw + 15)];
        const float4* k4 = reinterpret_cast<const float4*>(k_s + j * DH);
        float s = 0.f;
#pragma unroll
        for (int t = 0; t < 8; t++) {
            float4 kv = k4[t];
            s = fmaf(q[4 * t], kv.x, s);
            s = fmaf(q[4 * t + 1], kv.y, s);
            s = fmaf(q[4 * t + 2], kv.z, s);
            s = fmaf(q[4 * t + 3], kv.w, s);
        }
        float e = __expf((s + bias) * scale);
        l += e;
        const float4* v4 = reinterpret_cast<const float4*>(v_s + j * DH);
#pragma unroll
        for (int t = 0; t < 8; t++) {
            float4 vv = v4[t];
            o[4 * t]     = fmaf(e, vv.x, o[4 * t]);
            o[4 * t + 1] = fmaf(e, vv.y, o[4 * t + 1]);
            o[4 * t + 2] = fmaf(e, vv.z, o[4 * t + 2]);
            o[4 * t + 3] = fmaf(e, vv.w, o[4 * t + 3]);
        }
    }
    float inv = 1.f / l;
#pragma unroll
    for (int d = 0; d < DH; d++)
        outp[((size_t)(b * C1) + d * 4 + head) * HW + p] = o[d] * inv;
}

// ---------------- host orchestration ----------------
static float* sym_addr(const void* /*unused*/) { return nullptr; }

extern "C" void kernel_launch(void* const* d_in, const int* in_sizes, int n_in,
                              void* d_out, int out_size) {
    (void)in_sizes; (void)n_in; (void)out_size;
    const float* x        = (const float*)d_in[0];
    const float* bb_bn1_g = (const float*)d_in[1];
    const float* bb_bn1_b = (const float*)d_in[2];
    const float* bb_conv1 = (const float*)d_in[3];
    const float* bb_bn2_g = (const float*)d_in[4];
    const float* bb_bn2_b = (const float*)d_in[5];
    const float* bb_conv2 = (const float*)d_in[6];
    const float* bb_sbn_g = (const float*)d_in[7];
    const float* bb_sbn_b = (const float*)d_in[8];
    const float* bb_sconv = (const float*)d_in[9];
    const float* tb_bn1_g = (const float*)d_in[10];
    const float* tb_bn1_b = (const float*)d_in[11];
    const float* tb_dwqkv = (const float*)d_in[12];
    const float* tb_pwqkv = (const float*)d_in[13];
    const float* tb_dwout = (const float*)d_in[14];
    const float* tb_pwout = (const float*)d_in[15];
    const float* tb_rel   = (const float*)d_in[16];
    const float* tb_bn2_g = (const float*)d_in[17];
    const float* tb_bn2_b = (const float*)d_in[18];
    const float* tb_mlp   = (const float*)d_in[19];

    void* pv;
    float *pool, *t, *u, *o, *qkv;
    cudaGetSymbolAddress(&pv, g_pool); pool = (float*)pv;
    cudaGetSymbolAddress(&pv, g_t);    t    = (float*)pv;
    cudaGetSymbolAddress(&pv, g_u);    u    = (float*)pv;
    cudaGetSymbolAddress(&pv, g_o);    o    = (float*)pv;
    cudaGetSymbolAddress(&pv, g_qkv);  qkv  = (float*)pv;

    const int ATTN_SMEM = (2 * R2 * DH + 961) * sizeof(float);   // 69380 B
    cudaFuncSetAttribute(k_attn, cudaFuncAttributeMaxDynamicSharedMemorySize, 71680);

    dim3 cb3(16, 16);
    dim3 cg3(4, 4, 32);

    // ---- maxpool ----
    k_maxpool<<<(B * C0 * HW) / 256, 256>>>(x, pool);

    // ---- BasicBlock ----
    k_bnstats<<<C0, 256>>>(pool, bb_bn1_g, bb_bn1_b, C0);
    k_bnapply<<<(B * C0 * HW) / 256, 256>>>(pool, t, C0, 1);
    k_conv3<64><<<cg3, cb3>>>(t, bb_conv1, u);
    k_bnstats<<<C1, 256>>>(u, bb_bn2_g, bb_bn2_b, C1);
    k_bnapply<<<(B * C1 * HW) / 256, 256>>>(u, t, C1, 1);
    k_conv3<128><<<cg3, cb3>>>(t, bb_conv2, o);
    k_bnstats<<<C0, 256>>>(pool, bb_sbn_g, bb_sbn_b, C0);
    k_bnapply<<<(B * C0 * HW) / 256, 256>>>(pool, t, C0, 1);
    k_conv1<64><<<dim3(NPIX / 512, 128 / 16), 256>>>(t, bb_sconv, o, o, 128);

    // ---- 2 x BasicTransBlock ----
    for (int i = 0; i < 2; i++) {
        k_bnstats<<<C1, 256>>>(o, tb_bn1_g + i * 128, tb_bn1_b + i * 128, C1);
        k_bnapply<<<(B * C1 * HW) / 256, 256>>>(o, t, C1, 0);
        k_dw3<<<(B * C1 * HW) / 256, 256>>>(t, tb_dwqkv + (size_t)i * 128 * 9, u);
        k_conv1<128><<<dim3(NPIX / 512, 384 / 16), 256>>>(
            u, tb_pwqkv + (size_t)i * 384 * 128, qkv, nullptr, 384);
        k_ds<<<(B * 256 * R2) / 256, 256>>>(qkv);
        k_attn<<<dim3(HW / 256, B * 4), 256, ATTN_SMEM>>>(
            qkv, tb_rel + (size_t)i * 961 * 4, t);
        k_dw3<<<(B * C1 * HW) / 256, 256>>>(t, tb_dwout + (size_t)i * 128 * 9, u);
        k_conv1<128><<<dim3(NPIX / 512, 128 / 16), 256>>>(
            u, tb_pwout + (size_t)i * 128 * 128, o, o, 128);   // out = a + out
        k_bnstats<<<C1, 256>>>(o, tb_bn2_g + i * 128, tb_bn2_b + i * 128, C1);
        k_bnapply<<<(B * C1 * HW) / 256, 256>>>(o, t, C1, 1);
        float* dest = (i == 1) ? (float*)d_out : o;
        k_conv1<128><<<dim3(NPIX / 512, 128 / 16), 256>>>(
            t, tb_mlp + (size_t)i * 128 * 128, dest, o, 128);  // out = h + out
    }
}